// round 5
// baseline (speedup 1.0000x reference)
#include <cuda_runtime.h>
#include <math.h>

#define BB    8
#define CCH   64
#define C2    128
#define HH    224
#define WWID  224
#define HWSZ  (HH*WWID)          // 50176
#define NPIX  (BB*HWSZ)          // 401408

typedef unsigned long long ull;

// ---------------- packed f32x2 helpers ----------------
__device__ __forceinline__ ull pack2(float x) {
    ull r; asm("mov.b64 %0, {%1, %1};" : "=l"(r) : "f"(x)); return r;
}
__device__ __forceinline__ ull fma2(ull a, ull b, ull c) {
    ull d; asm("fma.rn.f32x2 %0, %1, %2, %3;" : "=l"(d) : "l"(a), "l"(b), "l"(c)); return d;
}
__device__ __forceinline__ ull add2(ull a, ull b) {
    ull d; asm("add.rn.f32x2 %0, %1, %2;" : "=l"(d) : "l"(a), "l"(b)); return d;
}
__device__ __forceinline__ ull mul2(ull a, ull b) {
    ull d; asm("mul.rn.f32x2 %0, %1, %2;" : "=l"(d) : "l"(a), "l"(b)); return d;
}

// ---------------- scratch (device globals; no allocation allowed) ----------------
static __device__ float g_buf2a[BB*C2*HWSZ];   // 205.5 MB
static __device__ float g_buf2b[BB*C2*HWSZ];   // 205.5 MB
static __device__ float g_bufc [BB*CCH*HWSZ];  // 102.8 MB
static __device__ float g_y    [BB*CCH*HWSZ];  // 102.8 MB
static __device__ float g_M    [C2*64*64];     // per-channel matrix [c][in][out]
static __device__ float g_dctR [CCH*56];
static __device__ float g_dctC [CCH*56];
static __device__ float g_instS[BB*CCH], g_instQ[BB*CCH];
static __device__ float g_instMean[BB*CCH], g_instInv[BB*CCH];
static __device__ float g_scay[BB*CCH], g_z[BB*CCH];

// ---------------- tiny init kernels ----------------
__global__ void k_zero() {
    int t = threadIdx.x;
    if (t < BB*CCH) { g_instS[t] = 0.f; g_instQ[t] = 0.f; g_scay[t] = 0.f; }
}

__global__ void k_tables() {
    int t = blockIdx.x * blockDim.x + threadIdx.x;
    if (t >= CCH*56) return;
    int c = t / 56, i = t - c*56;
    const int mx[16] = {0,0,6,0,0,1,1,4,5,1,3,0,0,0,3,2};
    const int my[16] = {0,1,0,5,2,0,2,0,0,6,0,4,6,3,2,5};
    int g = c >> 2;
    int ux = mx[g]*8, uy = my[g]*8;
    float inv = rsqrtf(56.f);
    float rv = cosf((float)M_PI * ux * (i + 0.5f) / 56.f) * inv;
    if (ux) rv *= 1.41421356237f;
    float cv = cosf((float)M_PI * uy * (i + 0.5f) / 56.f) * inv;
    if (uy) cv *= 1.41421356237f;
    g_dctR[t] = rv; g_dctC[t] = cv;
}

// M layout: g_M[c*4096 + in*64 + out]  (k-major for apply)
__global__ void k_fftmat(const float* __restrict__ fw) {
    int t = blockIdx.x * blockDim.x + threadIdx.x;
    if (t >= C2*64) return;
    int c = t >> 6, in = t & 63, i0 = in >> 3, j0 = in & 7;
    const float c8[8] = {1.f, 0.70710678118f, 0.f, -0.70710678118f,
                         -1.f, -0.70710678118f, 0.f, 0.70710678118f};
    const float s8[8] = {0.f, 0.70710678118f, 1.f, 0.70710678118f,
                         0.f, -0.70710678118f, -1.f, -0.70710678118f};
    for (int p = 0; p < 8; p++) {
        float Gr[5], Gi[5];
        for (int v = 0; v < 5; v++) {
            float gr = 0.f, gi = 0.f;
            for (int u = 0; u < 8; u++) {
                int idx = ((u*(p - i0) - v*j0) % 8 + 8) % 8;
                float w = fw[c*40 + u*5 + v];
                gr += w * c8[idx]; gi += w * s8[idx];
            }
            Gr[v] = gr; Gi[v] = gi;
        }
        for (int q = 0; q < 8; q++) {
            float val = Gr[0] + ((q & 1) ? -Gr[4] : Gr[4]);
            for (int v = 1; v < 4; v++) {
                int k = (v*q) & 7;
                val += 2.f * (Gr[v]*c8[k] - Gi[v]*s8[k]);
            }
            g_M[c*4096 + in*64 + (p*8 + q)] = val * (1.f/64.f);
        }
    }
}

// =====================================================================
// Unified GEMM: 64 in -> 64 out per block, 64 pixels/block, 128 threads.
// IMODE: 0 plain, 1 channel-LN, 2 z-scale, 3 gate-product (128-ch input)
// OMODE: 0 bias+store, 1 x + beta*(acc+bias) residual, 2 acc+add store
// Y-GEMMs (128 out) use gridDim.y = 2 (obase = blockIdx.y*64).
// smem: inT [64k][64px] (split-pixel layout) + wdup [64k][64oc] dup-ull = 48KB
// =====================================================================
template<int IMODE, int OMODE>
__global__ __launch_bounds__(128, 4) void k_gemm(
    const float* __restrict__ in, const float* __restrict__ w,
    const float* __restrict__ bias, const float* __restrict__ lnw,
    const float* __restrict__ lnb, float eps,
    const float* __restrict__ xres, const float* __restrict__ beta,
    const float* __restrict__ addsrc, float* __restrict__ out, int ocStride)
{
    __shared__ __align__(16) float inT[64*64];    // 16KB  [k][col]
    __shared__ __align__(16) ull   wdup[64*64];   // 32KB  [k][o] (value duplicated)
    int tid = threadIdx.x;
    int obase = blockIdx.y * 64;

    int pix0 = blockIdx.x * 64;
    int b = pix0 / HWSZ, hw0 = pix0 - b*HWSZ;

    // ---- weight staging: wdup[k*64+o] = dup(w[(obase+o)*64 + k]) ----
    for (int i = tid; i < 4096; i += 128) {
        int o = i & 63, k = i >> 6;
        wdup[k*64 + o] = pack2(__ldg(w + (obase + o)*64 + k));
    }

    // ---- input staging (conflict-free split layout) ----
    // col(p): pg=p>>3, r=p&7 -> pg*4 + (r&3) + (r>>2)*32
    if (IMODE == 1) {
        int p = tid >> 1, h = tid & 1;
        const float* src = in + (b*64 + h*32)*HWSZ + hw0 + p;
        float v[32];
#pragma unroll
        for (int c = 0; c < 32; c++) v[c] = src[c*HWSZ];
        float s = 0.f;
#pragma unroll
        for (int c = 0; c < 32; c++) s += v[c];
        s += __shfl_xor_sync(0xffffffffu, s, 1);
        float mu = s * (1.f/64.f);
        float q = 0.f;
#pragma unroll
        for (int c = 0; c < 32; c++) { float d = v[c]-mu; q += d*d; }
        q += __shfl_xor_sync(0xffffffffu, q, 1);
        float is = rsqrtf(q*(1.f/64.f) + eps);
        int pgp = p >> 3, r = p & 7;
        int colp = pgp*4 + (r & 3) + ((r >> 2) * 32);
#pragma unroll
        for (int c = 0; c < 32; c++) {
            int ch = h*32 + c;
            inT[ch*64 + colp] = (v[c]-mu)*is*__ldg(lnw+ch) + __ldg(lnb+ch);
        }
    } else {
        for (int i = tid; i < 4096; i += 128) {
            int c = i >> 6, p = i & 63;
            float val;
            if (IMODE == 3) {
                val = in[(b*128 + c)*HWSZ + hw0 + p] *
                      in[(b*128 + 64 + c)*HWSZ + hw0 + p];
            } else {
                val = in[(b*64 + c)*HWSZ + hw0 + p];
                if (IMODE == 2) val *= g_z[b*64 + c];
            }
            int pgp = p >> 3, r = p & 7;
            inT[c*64 + pgp*4 + (r & 3) + ((r >> 2) * 32)] = val;
        }
    }
    __syncthreads();

    // ---- mainloop: thread tile 8px x 4oc, manual k+1 prefetch ----
    int og = tid >> 3, pg = tid & 7;     // og 0..15, pg 0..7
    ull acc[4][4];
#pragma unroll
    for (int j = 0; j < 4; j++)
#pragma unroll
        for (int u = 0; u < 4; u++) acc[j][u] = 0ULL;

    const float* pB = inT + pg*4;
    const ull*   wB = wdup + og*4;

    ulonglong2 P0 = *(const ulonglong2*)(pB);
    ulonglong2 P1 = *(const ulonglong2*)(pB + 32);
    ulonglong2 W0 = *(const ulonglong2*)(wB);
    ulonglong2 W1 = *(const ulonglong2*)(wB + 2);

#pragma unroll
    for (int k = 0; k < 64; k++) {
        ulonglong2 nP0, nP1, nW0, nW1;
        if (k != 63) {
            nP0 = *(const ulonglong2*)(pB + (k+1)*64);
            nP1 = *(const ulonglong2*)(pB + (k+1)*64 + 32);
            nW0 = *(const ulonglong2*)(wB + (k+1)*64);
            nW1 = *(const ulonglong2*)(wB + (k+1)*64 + 2);
        }
        ull p0 = P0.x, p1 = P0.y, p2 = P1.x, p3 = P1.y;
        acc[0][0] = fma2(p0, W0.x, acc[0][0]);
        acc[0][1] = fma2(p1, W0.x, acc[0][1]);
        acc[0][2] = fma2(p2, W0.x, acc[0][2]);
        acc[0][3] = fma2(p3, W0.x, acc[0][3]);
        acc[1][0] = fma2(p0, W0.y, acc[1][0]);
        acc[1][1] = fma2(p1, W0.y, acc[1][1]);
        acc[1][2] = fma2(p2, W0.y, acc[1][2]);
        acc[1][3] = fma2(p3, W0.y, acc[1][3]);
        acc[2][0] = fma2(p0, W1.x, acc[2][0]);
        acc[2][1] = fma2(p1, W1.x, acc[2][1]);
        acc[2][2] = fma2(p2, W1.x, acc[2][2]);
        acc[2][3] = fma2(p3, W1.x, acc[2][3]);
        acc[3][0] = fma2(p0, W1.y, acc[3][0]);
        acc[3][1] = fma2(p1, W1.y, acc[3][1]);
        acc[3][2] = fma2(p2, W1.y, acc[3][2]);
        acc[3][3] = fma2(p3, W1.y, acc[3][3]);
        P0 = nP0; P1 = nP1; W0 = nW0; W1 = nW1;
    }

    // ---- epilogue ----
#pragma unroll
    for (int oj = 0; oj < 4; oj++) {
        int oc = obase + og*4 + oj;
        int off = (b*ocStride + oc)*HWSZ + hw0 + pg*8;
        ulonglong2 s0, s1;
        if (OMODE == 0) {
            ull b2 = bias ? pack2(__ldg(bias + oc)) : 0ULL;
            s0.x = add2(acc[oj][0], b2); s0.y = add2(acc[oj][1], b2);
            s1.x = add2(acc[oj][2], b2); s1.y = add2(acc[oj][3], b2);
        } else if (OMODE == 1) {
            ull b2 = pack2(__ldg(bias + oc));
            ull bt = pack2(__ldg(beta + oc));
            ulonglong2 x0 = *(const ulonglong2*)(xres + off);
            ulonglong2 x1 = *(const ulonglong2*)(xres + off + 4);
            s0.x = fma2(add2(acc[oj][0], b2), bt, x0.x);
            s0.y = fma2(add2(acc[oj][1], b2), bt, x0.y);
            s1.x = fma2(add2(acc[oj][2], b2), bt, x1.x);
            s1.y = fma2(add2(acc[oj][3], b2), bt, x1.y);
        } else {
            ulonglong2 a0 = *(const ulonglong2*)(addsrc + off);
            ulonglong2 a1 = *(const ulonglong2*)(addsrc + off + 4);
            s0.x = add2(acc[oj][0], a0.x); s0.y = add2(acc[oj][1], a0.y);
            s1.x = add2(acc[oj][2], a1.x); s1.y = add2(acc[oj][3], a1.y);
        }
        *(ulonglong2*)(out + off) = s0;
        *(ulonglong2*)(out + off + 4) = s1;
    }
}

// ---------------- depthwise 3x3 (+bias) with InstanceNorm stats ----------------
__global__ __launch_bounds__(256) void k_dw_stats(
    const float* __restrict__ in, const float* __restrict__ w,
    const float* __restrict__ bias, float* __restrict__ out)
{
    int bc = blockIdx.z;
    int c = bc & 127, b = bc >> 7;
    __shared__ float tile[10][34];
    __shared__ float redS[256], redQ[256];
    int tx0 = blockIdx.x*32, ty0 = blockIdx.y*8;
    int tid = threadIdx.y*32 + threadIdx.x;
    const float* src = in + bc*HWSZ;
    for (int i = tid; i < 340; i += 256) {
        int r = i/34, cc = i - r*34;
        int gy = ty0 + r - 1, gx = tx0 + cc - 1;
        tile[r][cc] = (gy >= 0 && gy < HH && gx >= 0 && gx < WWID) ? src[gy*WWID+gx] : 0.f;
    }
    __syncthreads();
    float acc = bias[c];
#pragma unroll
    for (int di = 0; di < 3; di++)
#pragma unroll
        for (int dj = 0; dj < 3; dj++)
            acc += w[c*9 + di*3 + dj] * tile[threadIdx.y+di][threadIdx.x+dj];
    out[bc*HWSZ + (ty0+threadIdx.y)*WWID + tx0 + threadIdx.x] = acc;

    if (c < 64) {
        redS[tid] = acc; redQ[tid] = acc*acc;
        __syncthreads();
        for (int s = 128; s > 0; s >>= 1) {
            if (tid < s) { redS[tid] += redS[tid+s]; redQ[tid] += redQ[tid+s]; }
            __syncthreads();
        }
        if (tid == 0) {
            atomicAdd(&g_instS[b*64 + c], redS[0]);
            atomicAdd(&g_instQ[b*64 + c], redQ[0]);
        }
    }
}

__global__ void k_instfin() {
    int t = blockIdx.x*blockDim.x + threadIdx.x;
    if (t < BB*CCH) {
        float m = g_instS[t] * (1.f/HWSZ);
        float v = g_instQ[t] * (1.f/HWSZ) - m*m;
        g_instMean[t] = m;
        g_instInv[t]  = rsqrtf(v + 1e-5f);
    }
}

// ---------------- instnorm(a)*g -> t3 (float4), DCT-weighted SCA pool ----------------
__global__ __launch_bounds__(256) void k_gate_sca4(
    const float* __restrict__ inw, const float* __restrict__ inb)
{
    int bc = blockIdx.y;
    int c = bc & 63, b = bc >> 6;
    int i4 = blockIdx.x*256 + threadIdx.x;
    const float4* A = (const float4*)(g_buf2b + (b*128 + c)*HWSZ);
    const float4* G = (const float4*)(g_buf2b + (b*128 + 64 + c)*HWSZ);
    float m = g_instMean[bc], iv = g_instInv[bc];
    float sw = inw[c], sb = inb[c];
    float4 a = A[i4], g = G[i4];
    float4 t;
    t.x = ((a.x - m)*iv*sw + sb) * g.x;
    t.y = ((a.y - m)*iv*sw + sb) * g.y;
    t.z = ((a.z - m)*iv*sw + sb) * g.z;
    t.w = ((a.w - m)*iv*sw + sb) * g.w;
    ((float4*)(g_bufc + bc*HWSZ))[i4] = t;
    int gy = i4 / 56, gx4 = i4 - gy*56;
    float ws = (t.x + t.y + t.z + t.w) * g_dctR[c*56 + (gy >> 2)] * g_dctC[c*56 + gx4];
    __shared__ float red[256];
    red[threadIdx.x] = ws; __syncthreads();
    for (int s = 128; s > 0; s >>= 1) {
        if (threadIdx.x < s) red[threadIdx.x] += red[threadIdx.x+s];
        __syncthreads();
    }
    if (threadIdx.x == 0) atomicAdd(&g_scay[bc], red[0]);
}

__global__ void k_se(const float* __restrict__ fc1, const float* __restrict__ fc2) {
    int b = blockIdx.x, c = threadIdx.x;
    __shared__ float ys[64];
    ys[c] = g_scay[b*64 + c] * (1.f/16.f);
    __syncthreads();
    float h[4];
#pragma unroll
    for (int j = 0; j < 4; j++) {
        float s = 0.f;
#pragma unroll
        for (int k = 0; k < 64; k++) s += fc1[j*64 + k] * ys[k];
        h[j] = fmaxf(s, 0.f);
    }
    float z = 0.f;
#pragma unroll
    for (int j = 0; j < 4; j++) z += fc2[c*4 + j] * h[j];
    g_z[b*64 + c] = 1.f / (1.f + expf(-z));
}

// ---------------- per-patch spectral transform (M resident per plane) ----------------
__global__ __launch_bounds__(128) void k_fftapply_rb() {
    int bc = blockIdx.x;
    int c  = bc & 127;
    __shared__ __align__(16) float Ms[4096];
    __shared__ __align__(16) float pat[64*60];
    int tid = threadIdx.x;
    const float* msrc = g_M + c*4096;
    for (int i = tid; i < 4096; i += 128) Ms[i] = msrc[i];
    const float* src = g_buf2b + bc*HWSZ;
    float* dstp = g_buf2a + bc*HWSZ;
    int og = tid & 15, pg = tid >> 4;
    for (int bp = 0; bp < 14; bp++) {
        for (int i = tid; i < 3584; i += 128) {
            int r = i / 224, wcol = i - r*224;
            int p = r & 7, band = r >> 3, pc = wcol >> 3, q = wcol & 7;
            pat[(p*8+q)*60 + band*28 + pc] = src[(bp*16 + r)*224 + wcol];
        }
        __syncthreads();
        ull acc[4][4];
#pragma unroll
        for (int j = 0; j < 4; j++)
#pragma unroll
            for (int u = 0; u < 4; u++) acc[j][u] = 0ULL;
        if (pg < 7) {
            const float* pI = pat + pg*8;
            for (int k = 0; k < 64; k++) {
                ulonglong2 va = *(const ulonglong2*)(pI + k*60);
                ulonglong2 vb = *(const ulonglong2*)(pI + k*60 + 4);
                float4 wv = *(const float4*)(Ms + k*64 + og*4);
                float wav[4] = {wv.x, wv.y, wv.z, wv.w};
#pragma unroll
                for (int j = 0; j < 4; j++) {
                    ull wp = pack2(wav[j]);
                    acc[j][0] = fma2(va.x, wp, acc[j][0]);
                    acc[j][1] = fma2(va.y, wp, acc[j][1]);
                    acc[j][2] = fma2(vb.x, wp, acc[j][2]);
                    acc[j][3] = fma2(vb.y, wp, acc[j][3]);
                }
            }
        }
        __syncthreads();
        if (pg < 7) {
#pragma unroll
            for (int j = 0; j < 4; j++) {
                int o = og*4 + j;
                ulonglong2 s0, s1;
                s0.x = acc[j][0]; s0.y = acc[j][1];
                s1.x = acc[j][2]; s1.y = acc[j][3];
                *(ulonglong2*)(pat + o*60 + pg*8) = s0;
                *(ulonglong2*)(pat + o*60 + pg*8 + 4) = s1;
            }
        }
        __syncthreads();
        for (int i = tid; i < 3584; i += 128) {
            int r = i / 224, wcol = i - r*224;
            int p = r & 7, band = r >> 3, pc = wcol >> 3, q = wcol & 7;
            dstp[(bp*16 + r)*224 + wcol] = pat[(p*8+q)*60 + band*28 + pc];
        }
        __syncthreads();
    }
}

// ---------------- DFFN depthwise 3x3 pair + gelu gate ----------------
__global__ __launch_bounds__(256) void k_dw_gelu(const float* __restrict__ w) {
    int bc = blockIdx.z;
    int c = bc & 63, b = bc >> 6;
    __shared__ float t1[10][34], t2[10][34];
    int tx0 = blockIdx.x*32, ty0 = blockIdx.y*8;
    int tid = threadIdx.y*32 + threadIdx.x;
    const float* s1 = g_buf2a + (b*128 + c)*HWSZ;
    const float* s2 = g_buf2a + (b*128 + 64 + c)*HWSZ;
    for (int i = tid; i < 340; i += 256) {
        int r = i/34, cc = i - r*34;
        int gy = ty0 + r - 1, gx = tx0 + cc - 1;
        bool ok = (gy >= 0 && gy < HH && gx >= 0 && gx < WWID);
        t1[r][cc] = ok ? s1[gy*WWID+gx] : 0.f;
        t2[r][cc] = ok ? s2[gy*WWID+gx] : 0.f;
    }
    __syncthreads();
    float d1 = 0.f, d2 = 0.f;
#pragma unroll
    for (int di = 0; di < 3; di++)
#pragma unroll
        for (int dj = 0; dj < 3; dj++) {
            d1 += w[c*9 + di*3 + dj]      * t1[threadIdx.y+di][threadIdx.x+dj];
            d2 += w[(64+c)*9 + di*3 + dj] * t2[threadIdx.y+di][threadIdx.x+dj];
        }
    float gel = 0.5f * d1 * (1.f + erff(d1 * 0.70710678118f));
    g_bufc[bc*HWSZ + (ty0+threadIdx.y)*WWID + tx0 + threadIdx.x] = gel * d2;
}

// ---------------- launch ----------------
extern "C" void kernel_launch(void* const* d_in, const int* in_sizes, int n_in,
                              void* d_out, int out_size)
{
    (void)in_sizes; (void)n_in; (void)out_size;
    const float* x       = (const float*)d_in[0];
    const float* n1_w    = (const float*)d_in[1];
    const float* n1_b    = (const float*)d_in[2];
    const float* conv1_w = (const float*)d_in[3];
    const float* conv1_b = (const float*)d_in[4];
    const float* conv2_w = (const float*)d_in[5];
    const float* conv2_b = (const float*)d_in[6];
    const float* in_w    = (const float*)d_in[7];
    const float* in_b    = (const float*)d_in[8];
    const float* fc1_w   = (const float*)d_in[9];
    const float* fc2_w   = (const float*)d_in[10];
    const float* conv3_w = (const float*)d_in[11];
    const float* conv3_b = (const float*)d_in[12];
    const float* beta    = (const float*)d_in[13];
    const float* n2n_w   = (const float*)d_in[14];
    const float* n2n_b   = (const float*)d_in[15];
    const float* conv4_w = (const float*)d_in[16];
    const float* conv4_b = (const float*)d_in[17];
    const float* conv5_w = (const float*)d_in[18];
    const float* conv5_b = (const float*)d_in[19];
    const float* ln_w    = (const float*)d_in[20];
    const float* ln_b    = (const float*)d_in[21];
    const float* pin_w   = (const float*)d_in[22];
    const float* dw_w    = (const float*)d_in[23];
    const float* fft_w   = (const float*)d_in[24];
    const float* pout_w  = (const float*)d_in[25];

    float *t2a, *t2b, *tc, *ty;
    cudaGetSymbolAddress((void**)&t2a, g_buf2a);
    cudaGetSymbolAddress((void**)&t2b, g_buf2b);
    cudaGetSymbolAddress((void**)&tc,  g_bufc);
    cudaGetSymbolAddress((void**)&ty,  g_y);

    const int GB = NPIX / 64;      // 6272 blocks (64 px each)
    dim3 gY(GB, 2), gX(GB, 1);

    k_zero<<<1, 512>>>();
    k_tables<<<28, 128>>>();
    k_fftmat<<<64, 128>>>(fft_w);

    // conv1: LN(n1) + 64->128 + bias  -> g_buf2a
    k_gemm<1,0><<<gY, 128>>>(x, conv1_w, conv1_b, n1_w, n1_b, 1e-6f,
                             nullptr, nullptr, nullptr, t2a, 128);

    // depthwise 3x3 + conv2 bias, InstanceNorm stats on 'a' half -> g_buf2b
    {
        dim3 g(7, 28, BB*C2), blk(32, 8);
        k_dw_stats<<<g, blk>>>(t2a, conv2_w, conv2_b, t2b);
    }
    k_instfin<<<4, 128>>>();

    // instnorm(a)*g -> t3 (g_bufc), DCT-weighted SCA pooling
    {
        dim3 g(HWSZ/(4*256), BB*CCH);
        k_gate_sca4<<<g, 256>>>(in_w, in_b);
    }
    k_se<<<BB, 64>>>(fc1_w, fc2_w);

    // conv3 on z-scaled t3 + residual -> g_buf2a
    k_gemm<2,1><<<gX, 128>>>(tc, conv3_w, conv3_b, nullptr, nullptr, 0.f,
                             x, beta, nullptr, t2a, 64);
    // conv4: LN(n2n) + 64->128 + bias (pre-gate) -> g_buf2b
    k_gemm<1,0><<<gY, 128>>>(t2a, conv4_w, conv4_b, n2n_w, n2n_b, 1e-6f,
                             nullptr, nullptr, nullptr, t2b, 128);
    // conv5 with gate-product staging -> y
    k_gemm<3,0><<<gX, 128>>>(t2b, conv5_w, conv5_b, nullptr, nullptr, 0.f,
                             nullptr, nullptr, nullptr, ty, 64);

    // DFFN: LN + pin (64->128) -> g_buf2b
    k_gemm<1,0><<<gY, 128>>>(ty, pin_w, nullptr, ln_w, ln_b, 1e-5f,
                             nullptr, nullptr, nullptr, t2b, 128);
    // patch spectral transform -> g_buf2a
    k_fftapply_rb<<<BB*C2, 128>>>();
    // depthwise pair + gelu gate -> g_bufc
    {
        dim3 g(7, 28, BB*CCH), blk(32, 8);
        k_dw_gelu<<<g, blk>>>(dw_w);
    }
    // pout + y -> d_out
    k_gemm<0,2><<<gX, 128>>>(tc, pout_w, nullptr, nullptr, nullptr, 0.f,
                             nullptr, nullptr, ty, (float*)d_out, 64);
}

// round 8
// speedup vs baseline: 1.6183x; 1.6183x over previous
#include <cuda_runtime.h>
#include <math.h>

#define BB    8
#define CCH   64
#define C2    128
#define HH    224
#define WWID  224
#define HWSZ  (HH*WWID)          // 50176
#define NPIX  (BB*HWSZ)          // 401408

typedef unsigned long long ull;

// ---------------- packed f32x2 helpers (used by fftapply) ----------------
__device__ __forceinline__ ull pack2(float x) {
    ull r; asm("mov.b64 %0, {%1, %1};" : "=l"(r) : "f"(x)); return r;
}
__device__ __forceinline__ ull fma2(ull a, ull b, ull c) {
    ull d; asm("fma.rn.f32x2 %0, %1, %2, %3;" : "=l"(d) : "l"(a), "l"(b), "l"(c)); return d;
}

// ---------------- tf32 mma helpers ----------------
__device__ __forceinline__ unsigned cvt_tf32(float f) {
    unsigned u; asm("cvt.rna.tf32.f32 %0, %1;" : "=r"(u) : "f"(f)); return u;
}
__device__ __forceinline__ void mma8(float* c, unsigned a0, unsigned a1,
                                     unsigned a2, unsigned a3, float bx, float by) {
    unsigned b0 = __float_as_uint(bx), b1 = __float_as_uint(by);
    asm("mma.sync.aligned.m16n8k8.row.col.f32.tf32.tf32.f32 "
        "{%0,%1,%2,%3}, {%4,%5,%6,%7}, {%8,%9}, {%0,%1,%2,%3};"
        : "+f"(c[0]), "+f"(c[1]), "+f"(c[2]), "+f"(c[3])
        : "r"(a0), "r"(a1), "r"(a2), "r"(a3), "r"(b0), "r"(b1));
}

// ---------------- scratch (device globals; no allocation allowed) ----------------
static __device__ float g_buf2a[BB*C2*HWSZ];
static __device__ float g_buf2b[BB*C2*HWSZ];
static __device__ float g_bufc [BB*CCH*HWSZ];
static __device__ float g_y    [BB*CCH*HWSZ];
static __device__ float g_M    [C2*64*64];     // [c][in][out]
static __device__ float g_dctR [CCH*56];
static __device__ float g_dctC [CCH*56];
static __device__ float g_instS[BB*CCH], g_instQ[BB*CCH];
static __device__ float g_instMean[BB*CCH], g_instInv[BB*CCH];
static __device__ float g_scay[BB*CCH], g_z[BB*CCH];

// ---------------- tiny init kernels ----------------
__global__ void k_zero() {
    int t = threadIdx.x;
    if (t < BB*CCH) { g_instS[t] = 0.f; g_instQ[t] = 0.f; g_scay[t] = 0.f; }
}

__global__ void k_tables() {
    int t = blockIdx.x * blockDim.x + threadIdx.x;
    if (t >= CCH*56) return;
    int c = t / 56, i = t - c*56;
    const int mx[16] = {0,0,6,0,0,1,1,4,5,1,3,0,0,0,3,2};
    const int my[16] = {0,1,0,5,2,0,2,0,0,6,0,4,6,3,2,5};
    int g = c >> 2;
    int ux = mx[g]*8, uy = my[g]*8;
    float inv = rsqrtf(56.f);
    float rv = cosf((float)M_PI * ux * (i + 0.5f) / 56.f) * inv;
    if (ux) rv *= 1.41421356237f;
    float cv = cosf((float)M_PI * uy * (i + 0.5f) / 56.f) * inv;
    if (uy) cv *= 1.41421356237f;
    g_dctR[t] = rv; g_dctC[t] = cv;
}

__global__ void k_fftmat(const float* __restrict__ fw) {
    int t = blockIdx.x * blockDim.x + threadIdx.x;
    if (t >= C2*64) return;
    int c = t >> 6, in = t & 63, i0 = in >> 3, j0 = in & 7;
    const float c8[8] = {1.f, 0.70710678118f, 0.f, -0.70710678118f,
                         -1.f, -0.70710678118f, 0.f, 0.70710678118f};
    const float s8[8] = {0.f, 0.70710678118f, 1.f, 0.70710678118f,
                         0.f, -0.70710678118f, -1.f, -0.70710678118f};
    for (int p = 0; p < 8; p++) {
        float Gr[5], Gi[5];
        for (int v = 0; v < 5; v++) {
            float gr = 0.f, gi = 0.f;
            for (int u = 0; u < 8; u++) {
                int idx = ((u*(p - i0) - v*j0) % 8 + 8) % 8;
                float w = fw[c*40 + u*5 + v];
                gr += w * c8[idx]; gi += w * s8[idx];
            }
            Gr[v] = gr; Gi[v] = gi;
        }
        for (int q = 0; q < 8; q++) {
            float val = Gr[0] + ((q & 1) ? -Gr[4] : Gr[4]);
            for (int v = 1; v < 4; v++) {
                int k = (v*q) & 7;
                val += 2.f * (Gr[v]*c8[k] - Gi[v]*s8[k]);
            }
            g_M[c*4096 + in*64 + (p*8 + q)] = val * (1.f/64.f);
        }
    }
}

// =====================================================================
// Tensor-core conv1x1 GEMM.  128 px x (NT*8) oc per block, K=64, tf32 mma.
// Static smem only: one 64*APAD buffer reused for A-stage then B-stage.
// IMODE: 0 plain, 1 channel-LN, 2 z-scale, 3 gate-product(128ch in)
// OMODE: 0 acc+bias, 1 x + beta*(acc+bias), 2 acc+add
// =====================================================================
#define APAD 136

template<int NT, int IMODE, int OMODE>
__global__ __launch_bounds__(256, 2) void k_tc(
    const float* __restrict__ in, const float* __restrict__ w,
    const float* __restrict__ bias, const float* __restrict__ lnw,
    const float* __restrict__ lnb, float eps,
    const float* __restrict__ xres, const float* __restrict__ beta,
    const float* __restrict__ addsrc, float* __restrict__ out, int ocStride)
{
    constexpr int NOC = NT*8;
    __shared__ __align__(16) float ABsm[64*APAD];   // 34.8KB: A stage, then B stage
    __shared__ float sbias[128];

    int tid = threadIdx.x;
    int pix0 = blockIdx.x*128;
    int b = pix0 / HWSZ, hw0 = pix0 - b*HWSZ;

    if (tid < NOC) sbias[tid] = bias ? __ldg(bias + tid) : 0.f;

    // ---- phase 1: stage A (activations), tf32, layout [c][px] pad APAD ----
    if (IMODE == 1) {
        int p = tid >> 1, h = tid & 1;
        const float* src = in + (b*64 + h*32)*HWSZ + hw0 + p;
        float v[32];
#pragma unroll
        for (int c = 0; c < 32; c++) v[c] = src[c*HWSZ];
        float s = 0.f;
#pragma unroll
        for (int c = 0; c < 32; c++) s += v[c];
        s += __shfl_xor_sync(0xffffffffu, s, 1);
        float mu = s * (1.f/64.f);
        float q = 0.f;
#pragma unroll
        for (int c = 0; c < 32; c++) { float d = v[c]-mu; q += d*d; }
        q += __shfl_xor_sync(0xffffffffu, q, 1);
        float is = rsqrtf(q*(1.f/64.f) + eps);
#pragma unroll
        for (int c = 0; c < 32; c++) {
            int ch = h*32 + c;
            float val = (v[c]-mu)*is*__ldg(lnw+ch) + __ldg(lnb+ch);
            ABsm[ch*APAD + p] = __uint_as_float(cvt_tf32(val));
        }
    } else {
        for (int i = tid; i < 8192; i += 256) {
            int px = i & 127, c = i >> 7;
            float val;
            if (IMODE == 3) {
                val = in[(b*128 + c)*HWSZ + hw0 + px] *
                      in[(b*128 + 64 + c)*HWSZ + hw0 + px];
            } else {
                val = in[(b*64 + c)*HWSZ + hw0 + px];
                if (IMODE == 2) val *= g_z[b*64 + c];
            }
            ABsm[c*APAD + px] = __uint_as_float(cvt_tf32(val));
        }
    }
    __syncthreads();

    // ---- phase 2: pull this warp's A fragments into registers ----
    int warp = tid >> 5, lane = tid & 31, g = lane >> 2, tig = lane & 3;
    int pxA = warp*16 + g;
    unsigned afrag[8][4];
#pragma unroll
    for (int kt = 0; kt < 8; kt++) {
        int ca = kt*8 + tig;
        afrag[kt][0] = __float_as_uint(ABsm[ca*APAD + pxA]);
        afrag[kt][1] = __float_as_uint(ABsm[ca*APAD + pxA + 8]);
        afrag[kt][2] = __float_as_uint(ABsm[(ca+4)*APAD + pxA]);
        afrag[kt][3] = __float_as_uint(ABsm[(ca+4)*APAD + pxA + 8]);
    }
    __syncthreads();

    // ---- phase 3: stage B (weights) into fragment layout (reuse buffer) ----
    for (int i = tid; i < NOC*64; i += 256) {
        int k = i & 63, oc = i >> 6;
        int kt = k >> 3, kk = k & 7, nt = oc >> 3, nn = oc & 7;
        unsigned v = cvt_tf32(__ldg(w + oc*64 + k));
        int idx = ((kt*(NT/2) + (nt>>1))*32 + nn*4 + (kk&3))*4 + ((nt&1)*2 + (kk>>2));
        ABsm[idx] = __uint_as_float(v);
    }
    __syncthreads();

    // ---- phase 4: MMA mainloop (A in regs, B from smem) ----
    float acc[NT][4];
#pragma unroll
    for (int nt = 0; nt < NT; nt++)
#pragma unroll
        for (int u = 0; u < 4; u++) acc[nt][u] = 0.f;

#pragma unroll
    for (int kt = 0; kt < 8; kt++) {
#pragma unroll
        for (int np = 0; np < NT/2; np++) {
            float4 bb = *(const float4*)&ABsm[((kt*(NT/2) + np)*32 + lane)*4];
            mma8(acc[2*np],   afrag[kt][0], afrag[kt][1], afrag[kt][2], afrag[kt][3], bb.x, bb.y);
            mma8(acc[2*np+1], afrag[kt][0], afrag[kt][1], afrag[kt][2], afrag[kt][3], bb.z, bb.w);
        }
    }

    // ---- epilogue ----
    int pxg = hw0 + warp*16 + g;
#pragma unroll
    for (int nt = 0; nt < NT; nt++) {
        int o0 = nt*8 + 2*tig, o1 = o0 + 1;
        int base0 = (b*ocStride + o0)*HWSZ + pxg;
        int base1 = (b*ocStride + o1)*HWSZ + pxg;
        float r0 = acc[nt][0], r1 = acc[nt][1], r2 = acc[nt][2], r3 = acc[nt][3];
        if (OMODE == 0) {
            float b0v = sbias[o0], b1v = sbias[o1];
            out[base0]     = r0 + b0v;
            out[base1]     = r1 + b1v;
            out[base0 + 8] = r2 + b0v;
            out[base1 + 8] = r3 + b1v;
        } else if (OMODE == 1) {
            float b0v = sbias[o0], b1v = sbias[o1];
            float bt0 = __ldg(beta + o0), bt1 = __ldg(beta + o1);
            out[base0]     = fmaf(r0 + b0v, bt0, __ldg(xres + base0));
            out[base1]     = fmaf(r1 + b1v, bt1, __ldg(xres + base1));
            out[base0 + 8] = fmaf(r2 + b0v, bt0, __ldg(xres + base0 + 8));
            out[base1 + 8] = fmaf(r3 + b1v, bt1, __ldg(xres + base1 + 8));
        } else {
            out[base0]     = r0 + __ldg(addsrc + base0);
            out[base1]     = r1 + __ldg(addsrc + base1);
            out[base0 + 8] = r2 + __ldg(addsrc + base0 + 8);
            out[base1 + 8] = r3 + __ldg(addsrc + base1 + 8);
        }
    }
}

// ---------------- depthwise 3x3 (+bias) with InstanceNorm stats ----------------
__global__ __launch_bounds__(256) void k_dw_stats(
    const float* __restrict__ in, const float* __restrict__ w,
    const float* __restrict__ bias, float* __restrict__ out)
{
    int bc = blockIdx.z;
    int c = bc & 127, b = bc >> 7;
    __shared__ float tile[10][34];
    __shared__ float redS[256], redQ[256];
    int tx0 = blockIdx.x*32, ty0 = blockIdx.y*8;
    int tid = threadIdx.y*32 + threadIdx.x;
    const float* src = in + bc*HWSZ;
    for (int i = tid; i < 340; i += 256) {
        int r = i/34, cc = i - r*34;
        int gy = ty0 + r - 1, gx = tx0 + cc - 1;
        tile[r][cc] = (gy >= 0 && gy < HH && gx >= 0 && gx < WWID) ? src[gy*WWID+gx] : 0.f;
    }
    __syncthreads();
    float acc = bias[c];
#pragma unroll
    for (int di = 0; di < 3; di++)
#pragma unroll
        for (int dj = 0; dj < 3; dj++)
            acc += w[c*9 + di*3 + dj] * tile[threadIdx.y+di][threadIdx.x+dj];
    out[bc*HWSZ + (ty0+threadIdx.y)*WWID + tx0 + threadIdx.x] = acc;

    if (c < 64) {
        redS[tid] = acc; redQ[tid] = acc*acc;
        __syncthreads();
        for (int s = 128; s > 0; s >>= 1) {
            if (tid < s) { redS[tid] += redS[tid+s]; redQ[tid] += redQ[tid+s]; }
            __syncthreads();
        }
        if (tid == 0) {
            atomicAdd(&g_instS[b*64 + c], redS[0]);
            atomicAdd(&g_instQ[b*64 + c], redQ[0]);
        }
    }
}

__global__ void k_instfin() {
    int t = blockIdx.x*blockDim.x + threadIdx.x;
    if (t < BB*CCH) {
        float m = g_instS[t] * (1.f/HWSZ);
        float v = g_instQ[t] * (1.f/HWSZ) - m*m;
        g_instMean[t] = m;
        g_instInv[t]  = rsqrtf(v + 1e-5f);
    }
}

// ---------------- instnorm(a)*g -> t3 (float4), DCT-weighted SCA pool ----------------
__global__ __launch_bounds__(256) void k_gate_sca4(
    const float* __restrict__ inw, const float* __restrict__ inb)
{
    int bc = blockIdx.y;
    int c = bc & 63, b = bc >> 6;
    int i4 = blockIdx.x*256 + threadIdx.x;
    const float4* A = (const float4*)(g_buf2b + (b*128 + c)*HWSZ);
    const float4* G = (const float4*)(g_buf2b + (b*128 + 64 + c)*HWSZ);
    float m = g_instMean[bc], iv = g_instInv[bc];
    float sw = inw[c], sb = inb[c];
    float4 a = A[i4], g = G[i4];
    float4 t;
    t.x = ((a.x - m)*iv*sw + sb) * g.x;
    t.y = ((a.y - m)*iv*sw + sb) * g.y;
    t.z = ((a.z - m)*iv*sw + sb) * g.z;
    t.w = ((a.w - m)*iv*sw + sb) * g.w;
    ((float4*)(g_bufc + bc*HWSZ))[i4] = t;
    int gy = i4 / 56, gx4 = i4 - gy*56;
    float ws = (t.x + t.y + t.z + t.w) * g_dctR[c*56 + (gy >> 2)] * g_dctC[c*56 + gx4];
    __shared__ float red[256];
    red[threadIdx.x] = ws; __syncthreads();
    for (int s = 128; s > 0; s >>= 1) {
        if (threadIdx.x < s) red[threadIdx.x] += red[threadIdx.x+s];
        __syncthreads();
    }
    if (threadIdx.x == 0) atomicAdd(&g_scay[bc], red[0]);
}

__global__ void k_se(const float* __restrict__ fc1, const float* __restrict__ fc2) {
    int b = blockIdx.x, c = threadIdx.x;
    __shared__ float ys[64];
    ys[c] = g_scay[b*64 + c] * (1.f/16.f);
    __syncthreads();
    float h[4];
#pragma unroll
    for (int j = 0; j < 4; j++) {
        float s = 0.f;
#pragma unroll
        for (int k = 0; k < 64; k++) s += fc1[j*64 + k] * ys[k];
        h[j] = fmaxf(s, 0.f);
    }
    float z = 0.f;
#pragma unroll
    for (int j = 0; j < 4; j++) z += fc2[c*4 + j] * h[j];
    g_z[b*64 + c] = 1.f / (1.f + expf(-z));
}

// ---------------- per-patch spectral transform (M resident per plane) ----------------
__global__ __launch_bounds__(128) void k_fftapply_rb() {
    int bc = blockIdx.x;
    int c  = bc & 127;
    __shared__ __align__(16) float Ms[4096];
    __shared__ __align__(16) float pat[64*60];
    int tid = threadIdx.x;
    const float* msrc = g_M + c*4096;
    for (int i = tid; i < 4096; i += 128) Ms[i] = msrc[i];
    const float* src = g_buf2b + bc*HWSZ;
    float* dstp = g_buf2a + bc*HWSZ;
    int og = tid & 15, pg = tid >> 4;
    for (int bp = 0; bp < 14; bp++) {
        for (int i = tid; i < 3584; i += 128) {
            int r = i / 224, wcol = i - r*224;
            int p = r & 7, band = r >> 3, pc = wcol >> 3, q = wcol & 7;
            pat[(p*8+q)*60 + band*28 + pc] = src[(bp*16 + r)*224 + wcol];
        }
        __syncthreads();
        ull acc[4][4];
#pragma unroll
        for (int j = 0; j < 4; j++)
#pragma unroll
            for (int u = 0; u < 4; u++) acc[j][u] = 0ULL;
        if (pg < 7) {
            const float* pI = pat + pg*8;
            for (int k = 0; k < 64; k++) {
                ulonglong2 va = *(const ulonglong2*)(pI + k*60);
                ulonglong2 vb = *(const ulonglong2*)(pI + k*60 + 4);
                float4 wv = *(const float4*)(Ms + k*64 + og*4);
                float wav[4] = {wv.x, wv.y, wv.z, wv.w};
#pragma unroll
                for (int j = 0; j < 4; j++) {
                    ull wp = pack2(wav[j]);
                    acc[j][0] = fma2(va.x, wp, acc[j][0]);
                    acc[j][1] = fma2(va.y, wp, acc[j][1]);
                    acc[j][2] = fma2(vb.x, wp, acc[j][2]);
                    acc[j][3] = fma2(vb.y, wp, acc[j][3]);
                }
            }
        }
        __syncthreads();
        if (pg < 7) {
#pragma unroll
            for (int j = 0; j < 4; j++) {
                int o = og*4 + j;
                ulonglong2 s0, s1;
                s0.x = acc[j][0]; s0.y = acc[j][1];
                s1.x = acc[j][2]; s1.y = acc[j][3];
                *(ulonglong2*)(pat + o*60 + pg*8) = s0;
                *(ulonglong2*)(pat + o*60 + pg*8 + 4) = s1;
            }
        }
        __syncthreads();
        for (int i = tid; i < 3584; i += 128) {
            int r = i / 224, wcol = i - r*224;
            int p = r & 7, band = r >> 3, pc = wcol >> 3, q = wcol & 7;
            dstp[(bp*16 + r)*224 + wcol] = pat[(p*8+q)*60 + band*28 + pc];
        }
        __syncthreads();
    }
}

// ---------------- DFFN depthwise 3x3 pair + gelu gate ----------------
__global__ __launch_bounds__(256) void k_dw_gelu(const float* __restrict__ w) {
    int bc = blockIdx.z;
    int c = bc & 63, b = bc >> 6;
    __shared__ float t1[10][34], t2[10][34];
    int tx0 = blockIdx.x*32, ty0 = blockIdx.y*8;
    int tid = threadIdx.y*32 + threadIdx.x;
    const float* s1 = g_buf2a + (b*128 + c)*HWSZ;
    const float* s2 = g_buf2a + (b*128 + 64 + c)*HWSZ;
    for (int i = tid; i < 340; i += 256) {
        int r = i/34, cc = i - r*34;
        int gy = ty0 + r - 1, gx = tx0 + cc - 1;
        bool ok = (gy >= 0 && gy < HH && gx >= 0 && gx < WWID);
        t1[r][cc] = ok ? s1[gy*WWID+gx] : 0.f;
        t2[r][cc] = ok ? s2[gy*WWID+gx] : 0.f;
    }
    __syncthreads();
    float d1 = 0.f, d2 = 0.f;
#pragma unroll
    for (int di = 0; di < 3; di++)
#pragma unroll
        for (int dj = 0; dj < 3; dj++) {
            d1 += w[c*9 + di*3 + dj]      * t1[threadIdx.y+di][threadIdx.x+dj];
            d2 += w[(64+c)*9 + di*3 + dj] * t2[threadIdx.y+di][threadIdx.x+dj];
        }
    float gel = 0.5f * d1 * (1.f + erff(d1 * 0.70710678118f));
    g_bufc[bc*HWSZ + (ty0+threadIdx.y)*WWID + tx0 + threadIdx.x] = gel * d2;
}

// ---------------- launch ----------------
extern "C" void kernel_launch(void* const* d_in, const int* in_sizes, int n_in,
                              void* d_out, int out_size)
{
    (void)in_sizes; (void)n_in; (void)out_size;
    const float* x       = (const float*)d_in[0];
    const float* n1_w    = (const float*)d_in[1];
    const float* n1_b    = (const float*)d_in[2];
    const float* conv1_w = (const float*)d_in[3];
    const float* conv1_b = (const float*)d_in[4];
    const float* conv2_w = (const float*)d_in[5];
    const float* conv2_b = (const float*)d_in[6];
    const float* in_w    = (const float*)d_in[7];
    const float* in_b    = (const float*)d_in[8];
    const float* fc1_w   = (const float*)d_in[9];
    const float* fc2_w   = (const float*)d_in[10];
    const float* conv3_w = (const float*)d_in[11];
    const float* conv3_b = (const float*)d_in[12];
    const float* beta    = (const float*)d_in[13];
    const float* n2n_w   = (const float*)d_in[14];
    const float* n2n_b   = (const float*)d_in[15];
    const float* conv4_w = (const float*)d_in[16];
    const float* conv4_b = (const float*)d_in[17];
    const float* conv5_w = (const float*)d_in[18];
    const float* conv5_b = (const float*)d_in[19];
    const float* ln_w    = (const float*)d_in[20];
    const float* ln_b    = (const float*)d_in[21];
    const float* pin_w   = (const float*)d_in[22];
    const float* dw_w    = (const float*)d_in[23];
    const float* fft_w   = (const float*)d_in[24];
    const float* pout_w  = (const float*)d_in[25];

    float *t2a, *t2b, *tc, *ty;
    cudaGetSymbolAddress((void**)&t2a, g_buf2a);
    cudaGetSymbolAddress((void**)&t2b, g_buf2b);
    cudaGetSymbolAddress((void**)&tc,  g_bufc);
    cudaGetSymbolAddress((void**)&ty,  g_y);

    const int GB = NPIX / 128;     // 3136 blocks (128 px each)

    k_zero<<<1, 512>>>();
    k_tables<<<28, 128>>>();
    k_fftmat<<<64, 128>>>(fft_w);

    // conv1: LN(n1) + 64->128 + bias  -> g_buf2a
    k_tc<16,1,0><<<GB, 256>>>(x, conv1_w, conv1_b, n1_w, n1_b, 1e-6f,
                              nullptr, nullptr, nullptr, t2a, 128);

    // depthwise 3x3 + conv2 bias, InstanceNorm stats on 'a' half -> g_buf2b
    {
        dim3 g(7, 28, BB*C2), blk(32, 8);
        k_dw_stats<<<g, blk>>>(t2a, conv2_w, conv2_b, t2b);
    }
    k_instfin<<<4, 128>>>();

    // instnorm(a)*g -> t3 (g_bufc), DCT-weighted SCA pooling
    {
        dim3 g(HWSZ/(4*256), BB*CCH);
        k_gate_sca4<<<g, 256>>>(in_w, in_b);
    }
    k_se<<<BB, 64>>>(fc1_w, fc2_w);

    // conv3 on z-scaled t3 + residual -> g_buf2a
    k_tc<8,2,1><<<GB, 256>>>(tc, conv3_w, conv3_b, nullptr, nullptr, 0.f,
                             x, beta, nullptr, t2a, 64);
    // conv4: LN(n2n) + 64->128 + bias (pre-gate) -> g_buf2b
    k_tc<16,1,0><<<GB, 256>>>(t2a, conv4_w, conv4_b, n2n_w, n2n_b, 1e-6f,
                              nullptr, nullptr, nullptr, t2b, 128);
    // conv5 with SimpleGate staging -> y
    k_tc<8,3,0><<<GB, 256>>>(t2b, conv5_w, conv5_b, nullptr, nullptr, 0.f,
                             nullptr, nullptr, nullptr, ty, 64);

    // DFFN: LN + pin (64->128) -> g_buf2b
    k_tc<16,1,0><<<GB, 256>>>(ty, pin_w, nullptr, ln_w, ln_b, 1e-5f,
                              nullptr, nullptr, nullptr, t2b, 128);
    // patch spectral transform -> g_buf2a
    k_fftapply_rb<<<BB*C2, 128>>>();
    // depthwise pair + gelu gate -> g_bufc
    {
        dim3 g(7, 28, BB*CCH), blk(32, 8);
        k_dw_gelu<<<g, blk>>>(dw_w);
    }
    // pout + y -> d_out
    k_tc<8,0,2><<<GB, 256>>>(tc, pout_w, nullptr, nullptr, nullptr, 0.f,
                             nullptr, nullptr, ty, (float*)d_out, 64);
}